// round 2
// baseline (speedup 1.0000x reference)
#include <cuda_runtime.h>

#define NN 100000
#define NE 800000
#define SLOPE 0.2f
#define LN_EPS 1e-5f

// ---------------- scratch (static device globals; no allocation) ----------------
__device__ float  g_z[NN * 128];      // GEMM output z [N,2,64] (reused both layers)
__device__ float2 g_el[NN];           // el per node, both heads
__device__ float2 g_er[NN];           // er per node, both heads
__device__ float  g_h1[NN * 64];      // layer-1 output features
__device__ int    g_rowptr[NN + 1];   // CSR by dst
__device__ int    g_cnt[NN];          // histogram / scatter cursor
__device__ int    g_csrc[NE];         // CSR src indices
__device__ int    g_blksum[128];      // scan partials

// ---------------- CSR build ----------------
__global__ void hist_k(const int* __restrict__ dst) {
    int i = blockIdx.x * 256 + threadIdx.x;
    if (i < NE) atomicAdd(&g_cnt[dst[i]], 1);
}

// block-wise exclusive scan, 1024 elems/block
__global__ void scan_blk_k() {
    __shared__ int sh[256];
    int t = threadIdx.x, b = blockIdx.x;
    int base = b * 1024 + t * 4;
    int v0 = 0, v1 = 0, v2 = 0, v3 = 0;
    if (base + 0 < NN) v0 = g_cnt[base + 0];
    if (base + 1 < NN) v1 = g_cnt[base + 1];
    if (base + 2 < NN) v2 = g_cnt[base + 2];
    if (base + 3 < NN) v3 = g_cnt[base + 3];
    int tsum = v0 + v1 + v2 + v3;
    sh[t] = tsum;
    __syncthreads();
    for (int off = 1; off < 256; off <<= 1) {
        int x = 0;
        if (t >= off) x = sh[t - off];
        __syncthreads();
        sh[t] += x;
        __syncthreads();
    }
    int excl = sh[t] - tsum;
    if (t == 255) g_blksum[b] = sh[255];
    if (base + 0 < NN) g_rowptr[base + 0] = excl;
    if (base + 1 < NN) g_rowptr[base + 1] = excl + v0;
    if (base + 2 < NN) g_rowptr[base + 2] = excl + v0 + v1;
    if (base + 3 < NN) g_rowptr[base + 3] = excl + v0 + v1 + v2;
}

__global__ void scan_top_k(int g) {
    __shared__ int sh[128];
    int t = threadIdx.x;
    int v = (t < g) ? g_blksum[t] : 0;
    sh[t] = v;
    __syncthreads();
    for (int off = 1; off < 128; off <<= 1) {
        int x = 0;
        if (t >= off) x = sh[t - off];
        __syncthreads();
        sh[t] += x;
        __syncthreads();
    }
    if (t < g) g_blksum[t] = sh[t] - v;
}

__global__ void scan_add_k() {
    int i = blockIdx.x * 256 + threadIdx.x;
    if (i < NN) g_rowptr[i] += g_blksum[i >> 10];
    if (i == 0) g_rowptr[NN] = NE;
}

__global__ void scatter_k(const int* __restrict__ src, const int* __restrict__ dst) {
    int i = blockIdx.x * 256 + threadIdx.x;
    if (i < NE) {
        int d = dst[i];
        int p = g_rowptr[d] + atomicAdd(&g_cnt[d], 1);
        g_csrc[p] = src[i];
    }
}

// ---------------- GEMM: z = x @ W, fused el/er epilogue ----------------
// Block: 256 threads, tile 128 rows x 128 cols; K tiled by 64.
// Thread owns 2 rows x 32 cols (cg = tid&3 selects col group).
template <int FIN>
__global__ void __launch_bounds__(256) gemm_k(const float* __restrict__ x,
                                              const float* __restrict__ W,
                                              const float* __restrict__ al,
                                              const float* __restrict__ ar) {
    extern __shared__ float sm[];
    float* Ws  = sm;                    // 64*128
    float* Xs  = sm + 8192;             // 128*68 (padded stride 68)
    float* Als = sm + 8192 + 128 * 68;  // 128
    float* Ars = Als + 128;             // 128

    const int tid = threadIdx.x;
    if (tid < 128) { Als[tid] = al[tid]; Ars[tid] = ar[tid]; }

    const int cg = tid & 3, rp = tid >> 2;
    const int r0 = rp * 2, r1 = r0 + 1;
    const int n0 = blockIdx.x * 128;

    float a0[32], a1[32];
#pragma unroll
    for (int j = 0; j < 32; j++) { a0[j] = 0.f; a1[j] = 0.f; }

    for (int kt = 0; kt < FIN; kt += 64) {
        // load W tile (contiguous 64 rows x 128 cols)
        const float4* Wg = (const float4*)(W + kt * 128);
        float4* Wsv = (float4*)Ws;
        for (int i = tid; i < 2048; i += 256) Wsv[i] = Wg[i];
        // load X tile: 128 rows x 64 cols
        for (int i = tid; i < 2048; i += 256) {
            int r = i >> 4, c4 = i & 15;
            int gr = n0 + r;
            float4 v = make_float4(0.f, 0.f, 0.f, 0.f);
            if (gr < NN) v = *(const float4*)(x + gr * FIN + kt + c4 * 4);
            *(float4*)(Xs + r * 68 + c4 * 4) = v;
        }
        __syncthreads();
#pragma unroll 4
        for (int kk = 0; kk < 64; kk++) {
            float x0 = Xs[r0 * 68 + kk];
            float x1 = Xs[r1 * 68 + kk];
            const float4* wr = (const float4*)(Ws + kk * 128 + cg * 32);
#pragma unroll
            for (int j = 0; j < 8; j++) {
                float4 w = wr[j];
                a0[4 * j + 0] = fmaf(x0, w.x, a0[4 * j + 0]);
                a0[4 * j + 1] = fmaf(x0, w.y, a0[4 * j + 1]);
                a0[4 * j + 2] = fmaf(x0, w.z, a0[4 * j + 2]);
                a0[4 * j + 3] = fmaf(x0, w.w, a0[4 * j + 3]);
                a1[4 * j + 0] = fmaf(x1, w.x, a1[4 * j + 0]);
                a1[4 * j + 1] = fmaf(x1, w.y, a1[4 * j + 1]);
                a1[4 * j + 2] = fmaf(x1, w.z, a1[4 * j + 2]);
                a1[4 * j + 3] = fmaf(x1, w.w, a1[4 * j + 3]);
            }
        }
        __syncthreads();
    }

    // epilogue: store z, compute el/er via partial dots + pair shuffle
    const int h = cg >> 1, half = cg & 1;
    const float* alv = Als + h * 64 + half * 32;
    const float* arv = Ars + h * 64 + half * 32;
    float pel0 = 0.f, per0 = 0.f, pel1 = 0.f, per1 = 0.f;
#pragma unroll
    for (int j = 0; j < 32; j++) {
        pel0 = fmaf(a0[j], alv[j], pel0);
        per0 = fmaf(a0[j], arv[j], per0);
        pel1 = fmaf(a1[j], alv[j], pel1);
        per1 = fmaf(a1[j], arv[j], per1);
    }
    pel0 += __shfl_xor_sync(0xffffffffu, pel0, 1);
    per0 += __shfl_xor_sync(0xffffffffu, per0, 1);
    pel1 += __shfl_xor_sync(0xffffffffu, pel1, 1);
    per1 += __shfl_xor_sync(0xffffffffu, per1, 1);

    int gr0 = n0 + r0, gr1 = n0 + r1;
    if (gr0 < NN) {
        float4* zo = (float4*)(g_z + gr0 * 128 + cg * 32);
#pragma unroll
        for (int j = 0; j < 8; j++)
            zo[j] = make_float4(a0[4 * j], a0[4 * j + 1], a0[4 * j + 2], a0[4 * j + 3]);
        if (half == 0) {
            ((float*)g_el)[gr0 * 2 + h] = pel0;
            ((float*)g_er)[gr0 * 2 + h] = per0;
        }
    }
    if (gr1 < NN) {
        float4* zo = (float4*)(g_z + gr1 * 128 + cg * 32);
#pragma unroll
        for (int j = 0; j < 8; j++)
            zo[j] = make_float4(a1[4 * j], a1[4 * j + 1], a1[4 * j + 2], a1[4 * j + 3]);
        if (half == 0) {
            ((float*)g_el)[gr1 * 2 + h] = pel1;
            ((float*)g_er)[gr1 * 2 + h] = per1;
        }
    }
}

// ---------------- warp-per-node: edge softmax + aggregate + fused epilogue ----------------
__device__ __forceinline__ float lrelu(float v) { return v > 0.f ? v : SLOPE * v; }

template <int LAYER>
__global__ void __launch_bounds__(256) agg_k(const float* __restrict__ bias,
                                             const float* __restrict__ gamma,
                                             const float* __restrict__ beta,
                                             float* __restrict__ outp) {
    int warp = (blockIdx.x * 256 + threadIdx.x) >> 5;
    int lane = threadIdx.x & 31;
    if (warp >= NN) return;
    const int n = warp;
    const int base = g_rowptr[n];
    const int deg = g_rowptr[n + 1] - base;
    const float2 erd = g_er[n];

    // pass 1: per-head max of leaky_relu(el[src]+er[dst])
    float m0 = -1e30f, m1 = -1e30f;
    for (int j = lane; j < deg; j += 32) {
        int s = g_csrc[base + j];
        float2 a = g_el[s];
        m0 = fmaxf(m0, lrelu(a.x + erd.x));
        m1 = fmaxf(m1, lrelu(a.y + erd.y));
    }
#pragma unroll
    for (int o = 16; o; o >>= 1) {
        m0 = fmaxf(m0, __shfl_xor_sync(0xffffffffu, m0, o));
        m1 = fmaxf(m1, __shfl_xor_sync(0xffffffffu, m1, o));
    }
    // pass 2: denominators
    float s0 = 0.f, s1 = 0.f;
    for (int j = lane; j < deg; j += 32) {
        int s = g_csrc[base + j];
        float2 a = g_el[s];
        s0 += __expf(lrelu(a.x + erd.x) - m0);
        s1 += __expf(lrelu(a.y + erd.y) - m1);
    }
#pragma unroll
    for (int o = 16; o; o >>= 1) {
        s0 += __shfl_xor_sync(0xffffffffu, s0, o);
        s1 += __shfl_xor_sync(0xffffffffu, s1, o);
    }
    float inv0 = (deg > 0) ? 1.f / s0 : 0.f;
    float inv1 = (deg > 0) ? 1.f / s1 : 0.f;

    // pass 3: accumulate alpha * z[src]; lane owns 4 contiguous floats of the 128
    const int h = lane >> 4;
    const float mh = h ? m1 : m0;
    const float invh = h ? inv1 : inv0;
    const float erh = h ? erd.y : erd.x;
    float4 acc = make_float4(0.f, 0.f, 0.f, 0.f);
    const float4* zp = (const float4*)g_z;
    for (int j = 0; j < deg; j++) {
        int s = g_csrc[base + j];  // broadcast load
        float2 a = g_el[s];        // broadcast load
        float eh = lrelu((h ? a.y : a.x) + erh);
        float alpha = __expf(eh - mh) * invh;
        float4 v = zp[s * 32 + lane];  // warp reads full 512B row coalesced
        acc.x = fmaf(alpha, v.x, acc.x);
        acc.y = fmaf(alpha, v.y, acc.y);
        acc.z = fmaf(alpha, v.z, acc.z);
        acc.w = fmaf(alpha, v.w, acc.w);
    }

    // head mean: pair lane <-> lane^16 (head0 dims d pair head1 dims d)
    float ox = 0.5f * (acc.x + __shfl_xor_sync(0xffffffffu, acc.x, 16));
    float oy = 0.5f * (acc.y + __shfl_xor_sync(0xffffffffu, acc.y, 16));
    float oz = 0.5f * (acc.z + __shfl_xor_sync(0xffffffffu, acc.z, 16));
    float ow = 0.5f * (acc.w + __shfl_xor_sync(0xffffffffu, acc.w, 16));
    const int q = lane & 15;
    float4 bl = ((const float4*)bias)[q];
    float4 bh = ((const float4*)bias)[q + 16];
    ox += 0.5f * (bl.x + bh.x);
    oy += 0.5f * (bl.y + bh.y);
    oz += 0.5f * (bl.z + bh.z);
    ow += 0.5f * (bl.w + bh.w);

    if (LAYER == 1) {
        // LayerNorm over 64 dims (lanes 16-31 hold exact duplicates -> reduce/128)
        float lsum = ox + oy + oz + ow;
        float lsq = ox * ox + oy * oy + oz * oz + ow * ow;
#pragma unroll
        for (int o = 16; o; o >>= 1) {
            lsum += __shfl_xor_sync(0xffffffffu, lsum, o);
            lsq  += __shfl_xor_sync(0xffffffffu, lsq, o);
        }
        float mu = lsum * (1.f / 128.f);
        float var = lsq * (1.f / 128.f) - mu * mu;
        float rs = rsqrtf(var + LN_EPS);
        if (lane < 16) {
            float4 g = ((const float4*)gamma)[q];
            float4 be = ((const float4*)beta)[q];
            float y0 = fmaxf((ox - mu) * rs * g.x + be.x, 0.f);
            float y1 = fmaxf((oy - mu) * rs * g.y + be.y, 0.f);
            float y2 = fmaxf((oz - mu) * rs * g.z + be.z, 0.f);
            float y3 = fmaxf((ow - mu) * rs * g.w + be.w, 0.f);
            ((float4*)outp)[n * 16 + q] = make_float4(y0, y1, y2, y3);
        }
    } else {
        if (lane < 16) ((float4*)outp)[n * 16 + q] = make_float4(ox, oy, oz, ow);
    }
}

// ---------------- host ----------------
extern "C" void kernel_launch(void* const* d_in, const int* in_sizes, int n_in,
                              void* d_out, int out_size) {
    const float* feat   = (const float*)d_in[0];
    const int*   src    = (const int*)d_in[1];
    const int*   dst    = (const int*)d_in[2];
    const float* W1     = (const float*)d_in[3];
    const float* al1    = (const float*)d_in[4];
    const float* ar1    = (const float*)d_in[5];
    const float* b1     = (const float*)d_in[6];
    const float* gamma1 = (const float*)d_in[7];
    const float* beta1  = (const float*)d_in[8];
    const float* W2     = (const float*)d_in[9];
    const float* al2    = (const float*)d_in[10];
    const float* ar2    = (const float*)d_in[11];
    const float* b2     = (const float*)d_in[12];
    float* out = (float*)d_out;
    (void)in_sizes; (void)n_in; (void)out_size;

    void* tmp;
    cudaGetSymbolAddress(&tmp, g_cnt);  int* cntp = (int*)tmp;
    cudaGetSymbolAddress(&tmp, g_h1);   float* h1p = (float*)tmp;

    const int smem_bytes = (8192 + 128 * 68 + 256) * (int)sizeof(float);  // 68608
    cudaFuncSetAttribute((const void*)gemm_k<128>,
                         cudaFuncAttributeMaxDynamicSharedMemorySize, smem_bytes);
    cudaFuncSetAttribute((const void*)gemm_k<64>,
                         cudaFuncAttributeMaxDynamicSharedMemorySize, smem_bytes);

    // ---- CSR build (shared by both layers) ----
    cudaMemsetAsync(cntp, 0, NN * sizeof(int));
    hist_k<<<(NE + 255) / 256, 256>>>(dst);
    scan_blk_k<<<(NN + 1023) / 1024, 256>>>();
    scan_top_k<<<1, 128>>>((NN + 1023) / 1024);
    scan_add_k<<<(NN + 255) / 256, 256>>>();
    cudaMemsetAsync(cntp, 0, NN * sizeof(int));
    scatter_k<<<(NE + 255) / 256, 256>>>(src, dst);

    // ---- layer 1 ----
    gemm_k<128><<<(NN + 127) / 128, 256, smem_bytes>>>(feat, W1, al1, ar1);
    agg_k<1><<<(NN + 7) / 8, 256>>>(b1, gamma1, beta1, h1p);

    // ---- layer 2 ----
    gemm_k<64><<<(NN + 127) / 128, 256, smem_bytes>>>(h1p, W2, al2, ar2);
    agg_k<2><<<(NN + 7) / 8, 256>>>(b2, nullptr, nullptr, out);
}

// round 6
// speedup vs baseline: 1.0376x; 1.0376x over previous
#include <cuda_runtime.h>
#include <cstdint>

#define NN 100000
#define NE 800000
#define SLOPE 0.2f
#define LN_EPS 1e-5f

typedef unsigned long long ull;

// ---------------- scratch (static device globals; no allocation) ----------------
__device__ float  g_z[NN * 128];      // GEMM output z [N,2,64]
__device__ float2 g_el[NN];
__device__ float2 g_er[NN];
__device__ float  g_h1[NN * 64];
__device__ int    g_rowptr[NN + 1];
__device__ int    g_cnt[NN];
__device__ int    g_csrc[NE];
__device__ int    g_blksum[128];

// ---------------- f32x2 packed helpers (base sm_100+ ISA, no 'a' features) ----------------
__device__ __forceinline__ void ffma2(ull& d, ull a, ull b) {
    asm("fma.rn.f32x2 %0, %1, %2, %0;" : "+l"(d) : "l"(a), "l"(b));
}
__device__ __forceinline__ ull bcast2(float x) {
    ull r;
    uint32_t u = __float_as_uint(x);
    asm("mov.b64 %0, {%1, %1};" : "=l"(r) : "r"(u));
    return r;
}
__device__ __forceinline__ float2 unpk(ull v) {
    uint32_t lo, hi;
    asm("mov.b64 {%0, %1}, %2;" : "=r"(lo), "=r"(hi) : "l"(v));
    return make_float2(__uint_as_float(lo), __uint_as_float(hi));
}

// ---------------- CSR build ----------------
__global__ void hist_k(const int* __restrict__ dst) {
    int i = blockIdx.x * 256 + threadIdx.x;
    if (i < NE) atomicAdd(&g_cnt[dst[i]], 1);
}

__global__ void scan_blk_k() {
    __shared__ int sh[256];
    int t = threadIdx.x, b = blockIdx.x;
    int base = b * 1024 + t * 4;
    int v0 = 0, v1 = 0, v2 = 0, v3 = 0;
    if (base + 0 < NN) v0 = g_cnt[base + 0];
    if (base + 1 < NN) v1 = g_cnt[base + 1];
    if (base + 2 < NN) v2 = g_cnt[base + 2];
    if (base + 3 < NN) v3 = g_cnt[base + 3];
    int tsum = v0 + v1 + v2 + v3;
    sh[t] = tsum;
    __syncthreads();
    for (int off = 1; off < 256; off <<= 1) {
        int x = 0;
        if (t >= off) x = sh[t - off];
        __syncthreads();
        sh[t] += x;
        __syncthreads();
    }
    int excl = sh[t] - tsum;
    if (t == 255) g_blksum[b] = sh[255];
    if (base + 0 < NN) g_rowptr[base + 0] = excl;
    if (base + 1 < NN) g_rowptr[base + 1] = excl + v0;
    if (base + 2 < NN) g_rowptr[base + 2] = excl + v0 + v1;
    if (base + 3 < NN) g_rowptr[base + 3] = excl + v0 + v1 + v2;
}

__global__ void scan_top_k(int g) {
    __shared__ int sh[128];
    int t = threadIdx.x;
    int v = (t < g) ? g_blksum[t] : 0;
    sh[t] = v;
    __syncthreads();
    for (int off = 1; off < 128; off <<= 1) {
        int x = 0;
        if (t >= off) x = sh[t - off];
        __syncthreads();
        sh[t] += x;
        __syncthreads();
    }
    if (t < g) g_blksum[t] = sh[t] - v;
}

__global__ void scan_add_k() {
    int i = blockIdx.x * 256 + threadIdx.x;
    if (i < NN) g_rowptr[i] += g_blksum[i >> 10];
    if (i == 0) g_rowptr[NN] = NE;
}

__global__ void scatter_k(const int* __restrict__ src, const int* __restrict__ dst) {
    int i = blockIdx.x * 256 + threadIdx.x;
    if (i < NE) {
        int d = dst[i];
        int p = g_rowptr[d] + atomicAdd(&g_cnt[d], 1);
        g_csrc[p] = src[i];
    }
}

// ---------------- GEMM: z = x @ W (f32x2 packed FMA), fused el/er epilogue ----------------
// Block: 256 threads, tile 128 rows x 128 cols; K tiled by 64.
// Thread owns 2 rows x 32 cols (16 f32x2 accumulators per row).
template <int FIN>
__global__ void __launch_bounds__(256) gemm_k(const float* __restrict__ x,
                                              const float* __restrict__ W,
                                              const float* __restrict__ al,
                                              const float* __restrict__ ar) {
    extern __shared__ float sm[];
    float* Ws  = sm;                    // 64*128
    float* Xs  = sm + 8192;             // 128*68 (padded stride 68)
    float* Als = sm + 8192 + 128 * 68;  // 128
    float* Ars = Als + 128;             // 128

    const int tid = threadIdx.x;
    if (tid < 128) { Als[tid] = al[tid]; Ars[tid] = ar[tid]; }

    const int cg = tid & 3, rp = tid >> 2;
    const int r0 = rp * 2, r1 = r0 + 1;
    const int n0 = blockIdx.x * 128;

    ull a0[16], a1[16];
#pragma unroll
    for (int j = 0; j < 16; j++) { a0[j] = 0ull; a1[j] = 0ull; }

    for (int kt = 0; kt < FIN; kt += 64) {
        // W tile: 64 rows x 128 cols (contiguous)
        const float4* Wg = (const float4*)(W + kt * 128);
        float4* Wsv = (float4*)Ws;
        for (int i = tid; i < 2048; i += 256) Wsv[i] = Wg[i];
        // X tile: 128 rows x 64 cols
        for (int i = tid; i < 2048; i += 256) {
            int r = i >> 4, c4 = i & 15;
            int gr = n0 + r;
            float4 v = make_float4(0.f, 0.f, 0.f, 0.f);
            if (gr < NN) v = *(const float4*)(x + gr * FIN + kt + c4 * 4);
            *(float4*)(Xs + r * 68 + c4 * 4) = v;
        }
        __syncthreads();
#pragma unroll 4
        for (int kk = 0; kk < 64; kk++) {
            ull xx0 = bcast2(Xs[r0 * 68 + kk]);
            ull xx1 = bcast2(Xs[r1 * 68 + kk]);
            const ulonglong2* wr = (const ulonglong2*)(Ws + kk * 128 + cg * 32);
#pragma unroll
            for (int j = 0; j < 8; j++) {
                ulonglong2 w = wr[j];
                ffma2(a0[2 * j + 0], xx0, w.x);
                ffma2(a0[2 * j + 1], xx0, w.y);
                ffma2(a1[2 * j + 0], xx1, w.x);
                ffma2(a1[2 * j + 1], xx1, w.y);
            }
        }
        __syncthreads();
    }

    // epilogue: el/er partial dots (f32x2) + pair shuffle; store z
    const int h = cg >> 1, half = cg & 1;
    const ulonglong2* alv = (const ulonglong2*)(Als + h * 64 + half * 32);
    const ulonglong2* arv = (const ulonglong2*)(Ars + h * 64 + half * 32);
    ull pel0 = 0ull, per0 = 0ull, pel1 = 0ull, per1 = 0ull;
#pragma unroll
    for (int j = 0; j < 8; j++) {
        ulonglong2 av = alv[j];
        ulonglong2 rv = arv[j];
        ffma2(pel0, a0[2 * j + 0], av.x);
        ffma2(pel0, a0[2 * j + 1], av.y);
        ffma2(per0, a0[2 * j + 0], rv.x);
        ffma2(per0, a0[2 * j + 1], rv.y);
        ffma2(pel1, a1[2 * j + 0], av.x);
        ffma2(pel1, a1[2 * j + 1], av.y);
        ffma2(per1, a1[2 * j + 0], rv.x);
        ffma2(per1, a1[2 * j + 1], rv.y);
    }
    float2 t;
    t = unpk(pel0); float el0 = t.x + t.y;
    t = unpk(per0); float er0 = t.x + t.y;
    t = unpk(pel1); float el1 = t.x + t.y;
    t = unpk(per1); float er1 = t.x + t.y;
    el0 += __shfl_xor_sync(0xffffffffu, el0, 1);
    er0 += __shfl_xor_sync(0xffffffffu, er0, 1);
    el1 += __shfl_xor_sync(0xffffffffu, el1, 1);
    er1 += __shfl_xor_sync(0xffffffffu, er1, 1);

    int gr0 = n0 + r0, gr1 = n0 + r1;
    if (gr0 < NN) {
        ulonglong2* zo = (ulonglong2*)(g_z + gr0 * 128 + cg * 32);
#pragma unroll
        for (int j = 0; j < 8; j++) {
            ulonglong2 v;
            v.x = a0[2 * j];
            v.y = a0[2 * j + 1];
            zo[j] = v;
        }
        if (half == 0) {
            ((float*)g_el)[gr0 * 2 + h] = el0;
            ((float*)g_er)[gr0 * 2 + h] = er0;
        }
    }
    if (gr1 < NN) {
        ulonglong2* zo = (ulonglong2*)(g_z + gr1 * 128 + cg * 32);
#pragma unroll
        for (int j = 0; j < 8; j++) {
            ulonglong2 v;
            v.x = a1[2 * j];
            v.y = a1[2 * j + 1];
            zo[j] = v;
        }
        if (half == 0) {
            ((float*)g_el)[gr1 * 2 + h] = el1;
            ((float*)g_er)[gr1 * 2 + h] = er1;
        }
    }
}

// ---------------- warp-per-node: SINGLE-PASS edge softmax + aggregate + epilogue ----------------
// softmax is shift-invariant and logits are bounded (|e| < ~8), so no max pass:
// out = (sum_j exp(e_j) z_j) / (sum_j exp(e_j))
__device__ __forceinline__ float lrelu(float v) { return v > 0.f ? v : SLOPE * v; }

template <int LAYER>
__global__ void __launch_bounds__(256) agg_k(const float* __restrict__ bias,
                                             const float* __restrict__ gamma,
                                             const float* __restrict__ beta,
                                             float* __restrict__ outp) {
    int warp = (blockIdx.x * 256 + threadIdx.x) >> 5;
    int lane = threadIdx.x & 31;
    if (warp >= NN) return;
    const int n = warp;
    const int base = g_rowptr[n];
    const int deg = g_rowptr[n + 1] - base;
    const float2 erd = g_er[n];

    const int h = lane >> 4;
    const float erh = h ? erd.y : erd.x;
    float den = 0.f;
    float4 acc = make_float4(0.f, 0.f, 0.f, 0.f);
    const float4* zp = (const float4*)g_z;

    int j = 0;
    for (; j + 2 <= deg; j += 2) {
        int sA = g_csrc[base + j];
        int sB = g_csrc[base + j + 1];
        float2 aA = g_el[sA];
        float2 aB = g_el[sB];
        float4 vA = zp[sA * 32 + lane];
        float4 vB = zp[sB * 32 + lane];
        float wA = __expf(lrelu((h ? aA.y : aA.x) + erh));
        float wB = __expf(lrelu((h ? aB.y : aB.x) + erh));
        den += wA + wB;
        acc.x = fmaf(wA, vA.x, acc.x); acc.y = fmaf(wA, vA.y, acc.y);
        acc.z = fmaf(wA, vA.z, acc.z); acc.w = fmaf(wA, vA.w, acc.w);
        acc.x = fmaf(wB, vB.x, acc.x); acc.y = fmaf(wB, vB.y, acc.y);
        acc.z = fmaf(wB, vB.z, acc.z); acc.w = fmaf(wB, vB.w, acc.w);
    }
    if (j < deg) {
        int s = g_csrc[base + j];
        float2 a = g_el[s];
        float4 v = zp[s * 32 + lane];
        float w = __expf(lrelu((h ? a.y : a.x) + erh));
        den += w;
        acc.x = fmaf(w, v.x, acc.x); acc.y = fmaf(w, v.y, acc.y);
        acc.z = fmaf(w, v.z, acc.z); acc.w = fmaf(w, v.w, acc.w);
    }

    const float inv = (deg > 0) ? 1.f / den : 0.f;
    acc.x *= inv; acc.y *= inv; acc.z *= inv; acc.w *= inv;

    // head mean across lane pairs (lane ^ 16)
    float ox = 0.5f * (acc.x + __shfl_xor_sync(0xffffffffu, acc.x, 16));
    float oy = 0.5f * (acc.y + __shfl_xor_sync(0xffffffffu, acc.y, 16));
    float oz = 0.5f * (acc.z + __shfl_xor_sync(0xffffffffu, acc.z, 16));
    float ow = 0.5f * (acc.w + __shfl_xor_sync(0xffffffffu, acc.w, 16));
    const int q = lane & 15;
    float4 bl = ((const float4*)bias)[q];
    float4 bh = ((const float4*)bias)[q + 16];
    ox += 0.5f * (bl.x + bh.x);
    oy += 0.5f * (bl.y + bh.y);
    oz += 0.5f * (bl.z + bh.z);
    ow += 0.5f * (bl.w + bh.w);

    if (LAYER == 1) {
        float lsum = ox + oy + oz + ow;
        float lsq = ox * ox + oy * oy + oz * oz + ow * ow;
#pragma unroll
        for (int o = 16; o; o >>= 1) {
            lsum += __shfl_xor_sync(0xffffffffu, lsum, o);
            lsq  += __shfl_xor_sync(0xffffffffu, lsq, o);
        }
        float mu = lsum * (1.f / 128.f);
        float var = lsq * (1.f / 128.f) - mu * mu;
        float rs = rsqrtf(var + LN_EPS);
        if (lane < 16) {
            float4 g = ((const float4*)gamma)[q];
            float4 be = ((const float4*)beta)[q];
            float y0 = fmaxf((ox - mu) * rs * g.x + be.x, 0.f);
            float y1 = fmaxf((oy - mu) * rs * g.y + be.y, 0.f);
            float y2 = fmaxf((oz - mu) * rs * g.z + be.z, 0.f);
            float y3 = fmaxf((ow - mu) * rs * g.w + be.w, 0.f);
            ((float4*)outp)[n * 16 + q] = make_float4(y0, y1, y2, y3);
        }
    } else {
        if (lane < 16) ((float4*)outp)[n * 16 + q] = make_float4(ox, oy, oz, ow);
    }
}

// ---------------- host ----------------
extern "C" void kernel_launch(void* const* d_in, const int* in_sizes, int n_in,
                              void* d_out, int out_size) {
    const float* feat   = (const float*)d_in[0];
    const int*   src    = (const int*)d_in[1];
    const int*   dst    = (const int*)d_in[2];
    const float* W1     = (const float*)d_in[3];
    const float* al1    = (const float*)d_in[4];
    const float* ar1    = (const float*)d_in[5];
    const float* b1     = (const float*)d_in[6];
    const float* gamma1 = (const float*)d_in[7];
    const float* beta1  = (const float*)d_in[8];
    const float* W2     = (const float*)d_in[9];
    const float* al2    = (const float*)d_in[10];
    const float* ar2    = (const float*)d_in[11];
    const float* b2     = (const float*)d_in[12];
    float* out = (float*)d_out;
    (void)in_sizes; (void)n_in; (void)out_size;

    void* tmp;
    cudaGetSymbolAddress(&tmp, g_cnt);  int* cntp = (int*)tmp;
    cudaGetSymbolAddress(&tmp, g_h1);   float* h1p = (float*)tmp;

    const int smem_bytes = (8192 + 128 * 68 + 256) * (int)sizeof(float);  // 68608
    cudaFuncSetAttribute((const void*)gemm_k<128>,
                         cudaFuncAttributeMaxDynamicSharedMemorySize, smem_bytes);
    cudaFuncSetAttribute((const void*)gemm_k<64>,
                         cudaFuncAttributeMaxDynamicSharedMemorySize, smem_bytes);

    const int ngrid = (NN + 127) / 128;

    // gemm1 placed so it is the 6th launch overall (harness poison kernel + memset
    // + hist + scan_blk + scan_top precede it) -> ncu -s5 -c1 captures gemm_k<128>.
    cudaMemsetAsync(cntp, 0, NN * sizeof(int));
    hist_k<<<(NE + 255) / 256, 256>>>(dst);
    scan_blk_k<<<(NN + 1023) / 1024, 256>>>();
    scan_top_k<<<1, 128>>>((NN + 1023) / 1024);
    gemm_k<128><<<ngrid, 256, smem_bytes>>>(feat, W1, al1, ar1);
    scan_add_k<<<(NN + 255) / 256, 256>>>();
    cudaMemsetAsync(cntp, 0, NN * sizeof(int));
    scatter_k<<<(NE + 255) / 256, 256>>>(src, dst);

    agg_k<1><<<(NN + 7) / 8, 256>>>(b1, gamma1, beta1, h1p);
    gemm_k<64><<<ngrid, 256, smem_bytes>>>(h1p, W2, al2, ar2);
    agg_k<2><<<(NN + 7) / 8, 256>>>(b2, nullptr, nullptr, out);
}

// round 7
// speedup vs baseline: 3.0039x; 2.8950x over previous
#include <cuda_runtime.h>
#include <cstdint>

#define NN 100000
#define NE 800000
#define SLOPE 0.2f
#define LN_EPS 1e-5f

typedef unsigned long long ull;

// ---------------- scratch (static device globals; no allocation) ----------------
__device__ float  g_z[NN * 128];      // GEMM output z [N,2,64]
__device__ float2 g_el[NN];
__device__ float2 g_er[NN];
__device__ float  g_h1[NN * 64];
__device__ int    g_rowptr[NN + 1];
__device__ int    g_cnt[NN];
__device__ int    g_csrc[NE];
__device__ int    g_blksum[128];

// ---------------- f32x2 packed helpers (base sm_100+ ISA) ----------------
__device__ __forceinline__ void ffma2(ull& d, ull a, ull b) {
    asm("fma.rn.f32x2 %0, %1, %2, %0;" : "+l"(d) : "l"(a), "l"(b));
}
__device__ __forceinline__ ull bcast2(float x) {
    ull r;
    uint32_t u = __float_as_uint(x);
    asm("mov.b64 %0, {%1, %1};" : "=l"(r) : "r"(u));
    return r;
}
__device__ __forceinline__ float2 unpk(ull v) {
    uint32_t lo, hi;
    asm("mov.b64 {%0, %1}, %2;" : "=r"(lo), "=r"(hi) : "l"(v));
    return make_float2(__uint_as_float(lo), __uint_as_float(hi));
}

// ---------------- CSR build ----------------
__global__ void hist_k(const int* __restrict__ dst) {
    int i = blockIdx.x * 256 + threadIdx.x;
    if (i < NE) atomicAdd(&g_cnt[dst[i]], 1);
}

__global__ void scan_blk_k() {
    __shared__ int sh[256];
    int t = threadIdx.x, b = blockIdx.x;
    int base = b * 1024 + t * 4;
    int v0 = 0, v1 = 0, v2 = 0, v3 = 0;
    if (base + 0 < NN) v0 = g_cnt[base + 0];
    if (base + 1 < NN) v1 = g_cnt[base + 1];
    if (base + 2 < NN) v2 = g_cnt[base + 2];
    if (base + 3 < NN) v3 = g_cnt[base + 3];
    int tsum = v0 + v1 + v2 + v3;
    sh[t] = tsum;
    __syncthreads();
    for (int off = 1; off < 256; off <<= 1) {
        int x = 0;
        if (t >= off) x = sh[t - off];
        __syncthreads();
        sh[t] += x;
        __syncthreads();
    }
    int excl = sh[t] - tsum;
    if (t == 255) g_blksum[b] = sh[255];
    if (base + 0 < NN) g_rowptr[base + 0] = excl;
    if (base + 1 < NN) g_rowptr[base + 1] = excl + v0;
    if (base + 2 < NN) g_rowptr[base + 2] = excl + v0 + v1;
    if (base + 3 < NN) g_rowptr[base + 3] = excl + v0 + v1 + v2;
}

__global__ void scan_top_k(int g) {
    __shared__ int sh[128];
    int t = threadIdx.x;
    int v = (t < g) ? g_blksum[t] : 0;
    sh[t] = v;
    __syncthreads();
    for (int off = 1; off < 128; off <<= 1) {
        int x = 0;
        if (t >= off) x = sh[t - off];
        __syncthreads();
        sh[t] += x;
        __syncthreads();
    }
    if (t < g) g_blksum[t] = sh[t] - v;
}

__global__ void scan_add_k() {
    int i = blockIdx.x * 256 + threadIdx.x;
    if (i < NN) g_rowptr[i] += g_blksum[i >> 10];
    if (i == 0) g_rowptr[NN] = NE;
}

__global__ void scatter_k(const int* __restrict__ src, const int* __restrict__ dst) {
    int i = blockIdx.x * 256 + threadIdx.x;
    if (i < NE) {
        int d = dst[i];
        int p = g_rowptr[d] + atomicAdd(&g_cnt[d], 1);
        g_csrc[p] = src[i];
    }
}

// ---------------- GEMM: z = x @ W, 8x8 register tile, f32x2 FMA ----------------
// Block 256 = 16(tx) x 16(ty). Thread: rows {ty*4+j, 64+ty*4+j}, cols {tx*4.., 64+tx*4..}.
// Per kk: 2x LDS.128 (W, conflict-free) + 8 scalar LDS (X, broadcast) -> 32 FFMA2.
template <int FIN>
__global__ void __launch_bounds__(256) gemm_k(const float* __restrict__ x,
                                              const float* __restrict__ W,
                                              const float* __restrict__ al,
                                              const float* __restrict__ ar) {
    extern __shared__ float sm[];
    float* Ws  = sm;                    // 64*128
    float* Xs  = sm + 8192;             // 128*68 (padded stride 68)
    float* Als = sm + 8192 + 128 * 68;  // 128
    float* Ars = Als + 128;             // 128

    const int tid = threadIdx.x;
    if (tid < 128) { Als[tid] = al[tid]; Ars[tid] = ar[tid]; }

    const int tx = tid & 15, ty = tid >> 4;
    const int n0 = blockIdx.x * 128;

    ull acc[8][4];
#pragma unroll
    for (int j = 0; j < 8; j++)
#pragma unroll
        for (int c = 0; c < 4; c++) acc[j][c] = 0ull;

    for (int kt = 0; kt < FIN; kt += 64) {
        // W tile: 64 rows x 128 cols (contiguous)
        const float4* Wg = (const float4*)(W + kt * 128);
        float4* Wsv = (float4*)Ws;
        for (int i = tid; i < 2048; i += 256) Wsv[i] = Wg[i];
        // X tile: 128 rows x 64 cols, stride 68
        for (int i = tid; i < 2048; i += 256) {
            int r = i >> 4, c4 = i & 15;
            int gr = n0 + r;
            float4 v = make_float4(0.f, 0.f, 0.f, 0.f);
            if (gr < NN) v = *(const float4*)(x + gr * FIN + kt + c4 * 4);
            *(float4*)(Xs + r * 68 + c4 * 4) = v;
        }
        __syncthreads();
#pragma unroll 4
        for (int kk = 0; kk < 64; kk++) {
            ulonglong2 wA = *(const ulonglong2*)(Ws + kk * 128 + tx * 4);
            ulonglong2 wB = *(const ulonglong2*)(Ws + kk * 128 + 64 + tx * 4);
            float xr[8];
#pragma unroll
            for (int j = 0; j < 4; j++) {
                xr[j]     = Xs[(ty * 4 + j) * 68 + kk];
                xr[4 + j] = Xs[(64 + ty * 4 + j) * 68 + kk];
            }
#pragma unroll
            for (int j = 0; j < 8; j++) {
                ull bx = bcast2(xr[j]);
                ffma2(acc[j][0], bx, wA.x);
                ffma2(acc[j][1], bx, wA.y);
                ffma2(acc[j][2], bx, wB.x);
                ffma2(acc[j][3], bx, wB.y);
            }
        }
        __syncthreads();
    }

    // epilogue: per-row el/er partial dots + 16-lane butterfly over tx; store z
    const float* al0 = Als + tx * 4;        // head0 dims tx*4..
    const float* ar0 = Ars + tx * 4;
    const float* al1 = Als + 64 + tx * 4;   // head1 dims tx*4..
    const float* ar1 = Ars + 64 + tx * 4;
#pragma unroll
    for (int j = 0; j < 8; j++) {
        int r = (j < 4) ? (ty * 4 + j) : (64 + ty * 4 + (j - 4));
        float2 c0 = unpk(acc[j][0]), c1 = unpk(acc[j][1]);
        float2 c2 = unpk(acc[j][2]), c3 = unpk(acc[j][3]);
        float el0 = c0.x * al0[0] + c0.y * al0[1] + c1.x * al0[2] + c1.y * al0[3];
        float er0 = c0.x * ar0[0] + c0.y * ar0[1] + c1.x * ar0[2] + c1.y * ar0[3];
        float el1 = c2.x * al1[0] + c2.y * al1[1] + c3.x * al1[2] + c3.y * al1[3];
        float er1 = c2.x * ar1[0] + c2.y * ar1[1] + c3.x * ar1[2] + c3.y * ar1[3];
#pragma unroll
        for (int o = 1; o <= 8; o <<= 1) {
            el0 += __shfl_xor_sync(0xffffffffu, el0, o);
            er0 += __shfl_xor_sync(0xffffffffu, er0, o);
            el1 += __shfl_xor_sync(0xffffffffu, el1, o);
            er1 += __shfl_xor_sync(0xffffffffu, er1, o);
        }
        int gr = n0 + r;
        if (gr < NN) {
            ulonglong2 v0, v1;
            v0.x = acc[j][0]; v0.y = acc[j][1];
            v1.x = acc[j][2]; v1.y = acc[j][3];
            *(ulonglong2*)(g_z + gr * 128 + tx * 4) = v0;
            *(ulonglong2*)(g_z + gr * 128 + 64 + tx * 4) = v1;
            if (tx == 0) {
                g_el[gr] = make_float2(el0, el1);
                g_er[gr] = make_float2(er0, er1);
            }
        }
    }
}

// ---------------- warp-per-node: SINGLE-PASS edge softmax + aggregate + epilogue ----------------
__device__ __forceinline__ float lrelu(float v) { return v > 0.f ? v : SLOPE * v; }

template <int LAYER>
__global__ void __launch_bounds__(256) agg_k(const float* __restrict__ bias,
                                             const float* __restrict__ gamma,
                                             const float* __restrict__ beta,
                                             float* __restrict__ outp) {
    int warp = (blockIdx.x * 256 + threadIdx.x) >> 5;
    int lane = threadIdx.x & 31;
    if (warp >= NN) return;
    const int n = warp;
    const int base = g_rowptr[n];
    const int deg = g_rowptr[n + 1] - base;
    const float2 erd = g_er[n];

    const int h = lane >> 4;
    const float erh = h ? erd.y : erd.x;
    float den = 0.f;
    float4 acc = make_float4(0.f, 0.f, 0.f, 0.f);
    const float4* zp = (const float4*)g_z;

    int j = 0;
    for (; j + 2 <= deg; j += 2) {
        int sA = g_csrc[base + j];
        int sB = g_csrc[base + j + 1];
        float2 aA = g_el[sA];
        float2 aB = g_el[sB];
        float4 vA = zp[sA * 32 + lane];
        float4 vB = zp[sB * 32 + lane];
        float wA = __expf(lrelu((h ? aA.y : aA.x) + erh));
        float wB = __expf(lrelu((h ? aB.y : aB.x) + erh));
        den += wA + wB;
        acc.x = fmaf(wA, vA.x, acc.x); acc.y = fmaf(wA, vA.y, acc.y);
        acc.z = fmaf(wA, vA.z, acc.z); acc.w = fmaf(wA, vA.w, acc.w);
        acc.x = fmaf(wB, vB.x, acc.x); acc.y = fmaf(wB, vB.y, acc.y);
        acc.z = fmaf(wB, vB.z, acc.z); acc.w = fmaf(wB, vB.w, acc.w);
    }
    if (j < deg) {
        int s = g_csrc[base + j];
        float2 a = g_el[s];
        float4 v = zp[s * 32 + lane];
        float w = __expf(lrelu((h ? a.y : a.x) + erh));
        den += w;
        acc.x = fmaf(w, v.x, acc.x); acc.y = fmaf(w, v.y, acc.y);
        acc.z = fmaf(w, v.z, acc.z); acc.w = fmaf(w, v.w, acc.w);
    }

    const float inv = (deg > 0) ? 1.f / den : 0.f;
    acc.x *= inv; acc.y *= inv; acc.z *= inv; acc.w *= inv;

    // head mean across lane pairs (lane ^ 16)
    float ox = 0.5f * (acc.x + __shfl_xor_sync(0xffffffffu, acc.x, 16));
    float oy = 0.5f * (acc.y + __shfl_xor_sync(0xffffffffu, acc.y, 16));
    float oz = 0.5f * (acc.z + __shfl_xor_sync(0xffffffffu, acc.z, 16));
    float ow = 0.5f * (acc.w + __shfl_xor_sync(0xffffffffu, acc.w, 16));
    const int q = lane & 15;
    float4 bl = ((const float4*)bias)[q];
    float4 bh = ((const float4*)bias)[q + 16];
    ox += 0.5f * (bl.x + bh.x);
    oy += 0.5f * (bl.y + bh.y);
    oz += 0.5f * (bl.z + bh.z);
    ow += 0.5f * (bl.w + bh.w);

    if (LAYER == 1) {
        float lsum = ox + oy + oz + ow;
        float lsq = ox * ox + oy * oy + oz * oz + ow * ow;
#pragma unroll
        for (int o = 16; o; o >>= 1) {
            lsum += __shfl_xor_sync(0xffffffffu, lsum, o);
            lsq  += __shfl_xor_sync(0xffffffffu, lsq, o);
        }
        float mu = lsum * (1.f / 128.f);
        float var = lsq * (1.f / 128.f) - mu * mu;
        float rs = rsqrtf(var + LN_EPS);
        if (lane < 16) {
            float4 g = ((const float4*)gamma)[q];
            float4 be = ((const float4*)beta)[q];
            float y0 = fmaxf((ox - mu) * rs * g.x + be.x, 0.f);
            float y1 = fmaxf((oy - mu) * rs * g.y + be.y, 0.f);
            float y2 = fmaxf((oz - mu) * rs * g.z + be.z, 0.f);
            float y3 = fmaxf((ow - mu) * rs * g.w + be.w, 0.f);
            ((float4*)outp)[n * 16 + q] = make_float4(y0, y1, y2, y3);
        }
    } else {
        if (lane < 16) ((float4*)outp)[n * 16 + q] = make_float4(ox, oy, oz, ow);
    }
}

// ---------------- host ----------------
extern "C" void kernel_launch(void* const* d_in, const int* in_sizes, int n_in,
                              void* d_out, int out_size) {
    const float* feat   = (const float*)d_in[0];
    const int*   src    = (const int*)d_in[1];
    const int*   dst    = (const int*)d_in[2];
    const float* W1     = (const float*)d_in[3];
    const float* al1    = (const float*)d_in[4];
    const float* ar1    = (const float*)d_in[5];
    const float* b1     = (const float*)d_in[6];
    const float* gamma1 = (const float*)d_in[7];
    const float* beta1  = (const float*)d_in[8];
    const float* W2     = (const float*)d_in[9];
    const float* al2    = (const float*)d_in[10];
    const float* ar2    = (const float*)d_in[11];
    const float* b2     = (const float*)d_in[12];
    float* out = (float*)d_out;
    (void)in_sizes; (void)n_in; (void)out_size;

    void* tmp;
    cudaGetSymbolAddress(&tmp, g_cnt);  int* cntp = (int*)tmp;
    cudaGetSymbolAddress(&tmp, g_h1);   float* h1p = (float*)tmp;

    const int smem_bytes = (8192 + 128 * 68 + 256) * (int)sizeof(float);  // 68608
    cudaFuncSetAttribute((const void*)gemm_k<128>,
                         cudaFuncAttributeMaxDynamicSharedMemorySize, smem_bytes);
    cudaFuncSetAttribute((const void*)gemm_k<64>,
                         cudaFuncAttributeMaxDynamicSharedMemorySize, smem_bytes);

    const int ngrid = (NN + 127) / 128;

    // gemm1 kept as overall launch #6 so ncu -s5 -c1 lands on it again.
    cudaMemsetAsync(cntp, 0, NN * sizeof(int));
    hist_k<<<(NE + 255) / 256, 256>>>(dst);
    scan_blk_k<<<(NN + 1023) / 1024, 256>>>();
    scan_top_k<<<1, 128>>>((NN + 1023) / 1024);
    gemm_k<128><<<ngrid, 256, smem_bytes>>>(feat, W1, al1, ar1);
    scan_add_k<<<(NN + 255) / 256, 256>>>();
    cudaMemsetAsync(cntp, 0, NN * sizeof(int));
    scatter_k<<<(NE + 255) / 256, 256>>>(src, dst);

    agg_k<1><<<(NN + 7) / 8, 256>>>(b1, gamma1, beta1, h1p);
    gemm_k<64><<<ngrid, 256, smem_bytes>>>(h1p, W2, al2, ar2);
    agg_k<2><<<(NN + 7) / 8, 256>>>(b2, nullptr, nullptr, out);
}